// round 15
// baseline (speedup 1.0000x reference)
#include <cuda_runtime.h>
#include <cstdint>
#include <cstddef>

#define NB 16
#define HH 256
#define WW 256
#define NPIX (NB * HH * WW)        // 1,048,576 pixels (per-channel BN count)
#define C1 128
#define C2 64

// ---------------- static device scratch (no allocations allowed) ----------------
__device__ uint32_t           g_xbits[NB * HH * (WW / 32)];   // packed sign(x), 128KB
__device__ unsigned long long g_wb1[C1];                      // 49-bit weight signs, layer1
__device__ uint4              g_wb2[C2];                      // 128-bit weight signs, layer2
__device__ unsigned long long g_s1[C1];                       // sum v1 (2's complement)
__device__ unsigned long long g_q1[C1];                       // sum v1^2
__device__ int                g_lo[C1];                       // v-interval lo (border path)
__device__ int                g_wd[C1];                       // v-interval width
__device__ int                g_ilo[C1];                      // d-interval lo (interior path)
__device__ int                g_iwd[C1];                      // d-interval width
__device__ unsigned long long g_sk[C2];                       // sum k
__device__ unsigned long long g_qk[C2];                       // sum k^2
__device__ float              g_P[C2], g_Q[C2];               // h2 = lrelu(P*k + Q)
__device__ uint32_t           g_d1[(size_t)32 * NPIX];        // 128MB: d packed 4ch/word, [cg][px]
// layer2 popcounts, channel-PAIR interleaved: [n][pair][px] as uchar2 (64MB)
__device__ unsigned char      g_k2p[(size_t)NB * 32 * HH * WW * 2];

// ---------------- packed f32x2 FMA (SASS FFMA2: 2 exact fp32 FMAs / issue slot) -----
__device__ __forceinline__ unsigned long long fma2(unsigned long long a,
                                                   unsigned long long b,
                                                   unsigned long long c) {
    unsigned long long d;
    asm("fma.rn.f32x2 %0, %1, %2, %3;" : "=l"(d) : "l"(a), "l"(b), "l"(c));
    return d;
}

// ---------------- pack sign(x) into bitmap; block 0 also packs weights + zeroes stats
__global__ void k_packx(const float* __restrict__ x,
                        const float* __restrict__ w1,
                        const float* __restrict__ w2) {
    int t = threadIdx.x;
    if (blockIdx.x == 0) {
        if (t < C1) {
            unsigned long long b = 0ull;
            #pragma unroll
            for (int j = 0; j < 49; j++)
                if (w1[t * 49 + j] >= 0.f) b |= (1ull << j);
            g_wb1[t] = b;
            g_s1[t] = 0ull;
            g_q1[t] = 0ull;
        }
        if (t < C2) {
            uint32_t w[4];
            #pragma unroll
            for (int q = 0; q < 4; q++) {
                uint32_t b = 0u;
                #pragma unroll
                for (int j = 0; j < 32; j++)
                    if (w2[t * 128 + q * 32 + j] >= 0.f) b |= (1u << j);
                w[q] = b;
            }
            g_wb2[t] = make_uint4(w[0], w[1], w[2], w[3]);
            g_sk[t] = 0ull;
            g_qk[t] = 0ull;
        }
    }
    int idx = blockIdx.x * 256 + t;
    unsigned b = __ballot_sync(0xFFFFFFFFu, x[idx] >= 0.f);
    if ((t & 31) == 0) g_xbits[idx >> 5] = b;
}

// ---------------- 7x7 window of sign bits + validity mask (border-safe) -------------
__device__ __forceinline__ void build_window(int n, int y, int x,
                                             unsigned long long& win,
                                             unsigned long long& msk) {
    const uint32_t* rowbase = g_xbits + (n << 11);
    uint32_t colmask = 0x7Fu;
    if (x < 3)   colmask &= (0x7Fu << (3 - x));
    if (x > 252) colmask &= (0x7Fu >> (x - 252));
    colmask &= 0x7Fu;
    int base = x - 3;
    int wi = (base >= 0) ? (base >> 5) : -1;
    int sh = base & 31;
    win = 0ull; msk = 0ull;
    #pragma unroll
    for (int r = 0; r < 7; r++) {
        int yy = y + r - 3;
        if (yy >= 0 && yy < HH) {
            const uint32_t* rw = rowbase + (yy << 3);
            uint32_t w0 = (wi >= 0) ? rw[wi] : 0u;
            uint32_t w1 = (wi < 7) ? rw[wi + 1] : 0u;
            uint32_t bits = __funnelshift_r(w0, w1, sh) & colmask;
            win |= (unsigned long long)bits << (7 * r);
            msk |= (unsigned long long)colmask << (7 * r);
        }
    }
}

// ---------------- unguarded interior window from shared row bits --------------------
__device__ __forceinline__ unsigned long long win_from_rows(const uint32_t* rb) {
    unsigned long long w = 0ull;
    #pragma unroll
    for (int r = 0; r < 7; r++)
        w |= (unsigned long long)rb[r] << (7 * r);
    return w;
}

// ---------------- pass 1: layer1 conv -> per-channel integer stats + packed d store --
__global__ void k_conv1_stats() {
    __shared__ unsigned long long s_wb[C1];
    __shared__ int s_sum[C1];
    __shared__ int s_sq[C1];
    int t = threadIdx.x;
    if (t < C1) { s_wb[t] = g_wb1[t]; s_sum[t] = 0; s_sq[t] = 0; }
    __syncthreads();

    int base = blockIdx.x * 2048 + t;
    int n  = base >> 16;
    int r0 = (blockIdx.x * 8) & 255;     // first of 8 rows this block covers
    int x  = t;                          // column (block spans full rows)
    int lane = t & 31;
    int xw = t & 224;                    // warp x-start (multiple of 32)
    bool wint = (xw != 0) && (xw != 224) && (r0 >= 8) && (r0 <= 240);

    if (wint) {
        // ---- interior fast path: unmasked windows ----
        const uint32_t* rowbase = g_xbits + (n << 11);
        int bm3 = x - 3;
        int wi = bm3 >> 5;
        int sh = bm3 & 31;
        uint32_t rb[14];
        #pragma unroll
        for (int j = 0; j < 14; j++) {
            const uint32_t* rw = rowbase + ((r0 - 3 + j) << 3);
            rb[j] = __funnelshift_r(rw[wi], rw[wi + 1], sh) & 0x7Fu;
        }
        unsigned long long win[8];
        #pragma unroll
        for (int k = 0; k < 8; k++) win[k] = win_from_rows(rb + k);

        #pragma unroll 2
        for (int cg = 0; cg < 32; cg++) {
            unsigned long long wb0 = s_wb[4 * cg + 0];
            unsigned long long wb1 = s_wb[4 * cg + 1];
            unsigned long long wb2 = s_wb[4 * cg + 2];
            unsigned long long wb3 = s_wb[4 * cg + 3];
            int sd0 = 0, sd1 = 0, sd2 = 0, sd3 = 0;
            int q0 = 0, q1 = 0, q2 = 0, q3 = 0;
            #pragma unroll
            for (int k = 0; k < 8; k++) {
                int d0 = __popcll(win[k] ^ wb0);
                int d1 = __popcll(win[k] ^ wb1);
                int d2 = __popcll(win[k] ^ wb2);
                int d3 = __popcll(win[k] ^ wb3);
                sd0 += d0; q0 += d0 * d0;
                sd1 += d1; q1 += d1 * d1;
                sd2 += d2; q2 += d2 * d2;
                sd3 += d3; q3 += d3 * d3;
                g_d1[((size_t)cg << 20) + base + k * 256] =
                    (unsigned)d0 | ((unsigned)d1 << 8) |
                    ((unsigned)d2 << 16) | ((unsigned)d3 << 24);
            }
            #pragma unroll
            for (int j = 0; j < 4; j++) {
                int sd = (j == 0) ? sd0 : (j == 1) ? sd1 : (j == 2) ? sd2 : sd3;
                int qq = (j == 0) ? q0  : (j == 1) ? q1  : (j == 2) ? q2  : q3;
                int Sd  = __reduce_add_sync(0xFFFFFFFFu, sd);
                int Sdd = __reduce_add_sync(0xFFFFFFFFu, qq);
                if (lane == 0) {
                    // 256 px/warp: sum v = 256*49 - 2*Sd ; sum v^2 = 256*2401 - 196*Sd + 4*Sdd
                    atomicAdd(&s_sum[4 * cg + j], 12544 - 2 * Sd);
                    atomicAdd(&s_sq[4 * cg + j], 614656 - 196 * Sd + 4 * Sdd);
                }
            }
        }
    } else {
        // ---- border path (exact masks) ----
        unsigned long long win[8], msk[8];
        int inb[8];
        #pragma unroll
        for (int k = 0; k < 8; k++) {
            int p = base + k * 256;
            int rem = p & 65535;
            build_window(n, rem >> 8, rem & 255, win[k], msk[k]);
            inb[k] = __popcll(msk[k]);
        }
        #pragma unroll 2
        for (int cg = 0; cg < 32; cg++) {
            unsigned long long wb0 = s_wb[4 * cg + 0];
            unsigned long long wb1 = s_wb[4 * cg + 1];
            unsigned long long wb2 = s_wb[4 * cg + 2];
            unsigned long long wb3 = s_wb[4 * cg + 3];
            int s0 = 0, s1 = 0, s2 = 0, s3 = 0;
            int q0 = 0, q1 = 0, q2 = 0, q3 = 0;
            #pragma unroll
            for (int k = 0; k < 8; k++) {
                int d0 = __popcll((win[k] ^ wb0) & msk[k]);
                int d1 = __popcll((win[k] ^ wb1) & msk[k]);
                int d2 = __popcll((win[k] ^ wb2) & msk[k]);
                int d3 = __popcll((win[k] ^ wb3) & msk[k]);
                g_d1[((size_t)cg << 20) + base + k * 256] =
                    (unsigned)d0 | ((unsigned)d1 << 8) |
                    ((unsigned)d2 << 16) | ((unsigned)d3 << 24);
                int v0 = inb[k] - 2 * d0;
                int v1 = inb[k] - 2 * d1;
                int v2 = inb[k] - 2 * d2;
                int v3 = inb[k] - 2 * d3;
                s0 += v0; q0 += v0 * v0;
                s1 += v1; q1 += v1 * v1;
                s2 += v2; q2 += v2 * v2;
                s3 += v3; q3 += v3 * v3;
            }
            #pragma unroll
            for (int j = 0; j < 4; j++) {
                int ss = (j == 0) ? s0 : (j == 1) ? s1 : (j == 2) ? s2 : s3;
                int qq = (j == 0) ? q0 : (j == 1) ? q1 : (j == 2) ? q2 : q3;
                int S  = __reduce_add_sync(0xFFFFFFFFu, ss);
                int Q  = __reduce_add_sync(0xFFFFFFFFu, qq);
                if (lane == 0) {
                    atomicAdd(&s_sum[4 * cg + j], S);
                    atomicAdd(&s_sq[4 * cg + j], Q);
                }
            }
        }
    }
    __syncthreads();
    if (t < C1) {
        atomicAdd(&g_s1[t], (unsigned long long)(long long)s_sum[t]);
        atomicAdd(&g_q1[t], (unsigned long long)(long long)s_sq[t]);
    }
}

// ---------------- finalize BN1 -> sign-threshold intervals (v and d domains) --------
__global__ void k_fin1(const float* __restrict__ g1, const float* __restrict__ b1) {
    int c = threadIdx.x;
    if (c >= C1) return;
    double N = (double)NPIX;
    double S1 = (double)(long long)g_s1[c];
    double S2 = (double)g_q1[c];
    double mean = S1 / N;
    double var  = S2 / N - mean * mean;
    float meanf = (float)mean;
    float invf  = g1[c] * rsqrtf((float)var + 1e-5f);
    float beta  = b1[c];
    int lo = 100, hi = -100;
    bool any = false;
    for (int v = -49; v <= 49; v++) {
        float h = ((float)v - meanf) * invf + beta;
        if (h >= 0.f) { if (!any) { lo = v; any = true; } hi = v; }
    }
    int ilo = 100, iwd = 0;                 // d-interval for interior (v = 49-2d)
    if (!any) { g_lo[c] = 100; g_wd[c] = 0; }
    else {
        g_lo[c] = lo;  g_wd[c] = hi - lo;
        int dlo = (49 - hi + 1) >> 1;       // ceil((49-hi)/2)
        int dhi = (49 - lo) >> 1;           // floor((49-lo)/2)
        if (dlo < 0) dlo = 0;
        if (dhi > 49) dhi = 49;
        if (dhi >= dlo) { ilo = dlo; iwd = dhi - dlo; }
    }
    g_ilo[c] = ilo; g_iwd[c] = iwd;
}

// ---------------- pass 2: stored d -> SWAR threshold -> layer2 1x1 binary conv ------
// Block order REVERSED: reads the most-recently-written (still-L2-resident) tail
// of g_d1 first. Body identical to the measured 92.7us R11/R14 version.
__global__ void k_sign_conv2() {
    __shared__ unsigned long long s_wb[C1];
    __shared__ int2 s_vi[C1];          // (lo, wd)  border, v-domain
    __shared__ unsigned s_LO[32];      // packed lo bytes (4 ch/word)
    __shared__ unsigned s_HIO[32];     // packed (hi|0x80) bytes
    __shared__ uint4 s_w2[C2];
    int t = threadIdx.x;
    if (t < C1) {
        s_wb[t] = g_wb1[t];
        s_vi[t] = make_int2(g_lo[t], g_wd[t]);
    }
    if (t < 32) {
        unsigned lo = 0, hio = 0;
        #pragma unroll
        for (int j = 0; j < 4; j++) {
            int c = 4 * t + j;
            lo  |= (unsigned)g_ilo[c] << (8 * j);
            hio |= (unsigned)((g_ilo[c] + g_iwd[c]) | 0x80) << (8 * j);
        }
        s_LO[t] = lo; s_HIO[t] = hio;
    }
    if (t < C2) s_w2[t] = g_wb2[t];
    __syncthreads();

    int bid = (int)gridDim.x - 1 - (int)blockIdx.x;   // reversed block order
    int p = bid * 256 + t;
    int n = p >> 16;
    int rem = p & 65535;
    int y = rem >> 8;                  // block-uniform (one row per block)
    int xw = t & 224;
    bool wint = (xw != 0) && (xw != 224) && (y >= 3) && (y <= 252);

    uint32_t sw[4];
    if (wint) {
        unsigned m0 = 0, m1 = 0, m2 = 0, m3 = 0;
        #pragma unroll
        for (int cg = 0; cg < 32; cg++) {
            unsigned D = g_d1[((size_t)cg << 20) + p];
            unsigned ge = (D | 0x80808080u) - s_LO[cg];
            unsigned le = s_HIO[cg] - D;
            unsigned both = ge & le & 0x80808080u;
            unsigned nib = (((both >> 7) * 0x01020408u) >> 24) & 0xFu;
            unsigned sh = 4 * (cg & 7);
            if ((cg >> 3) == 0) m0 |= nib << sh;
            else if ((cg >> 3) == 1) m1 |= nib << sh;
            else if ((cg >> 3) == 2) m2 |= nib << sh;
            else m3 |= nib << sh;
        }
        sw[0] = m0; sw[1] = m1; sw[2] = m2; sw[3] = m3;
    } else {
        unsigned long long win, msk;
        build_window(n, y, t, win, msk);
        int inb = __popcll(msk);
        #pragma unroll
        for (int w = 0; w < 4; w++) {
            uint32_t bits = 0u;
            #pragma unroll
            for (int j = 0; j < 32; j++) {
                int c = w * 32 + j;
                int dis = __popcll((win ^ s_wb[c]) & msk);
                int v = inb - 2 * dis;
                int2 vi = s_vi[c];
                if ((unsigned)(v - vi.x) <= (unsigned)vi.y) bits |= (1u << j);
            }
            sw[w] = bits;
        }
    }

    unsigned char* outp = g_k2p + ((size_t)n << 22) + 2 * (size_t)rem;
    #pragma unroll 8
    for (int p2 = 0; p2 < 32; p2++) {
        uint4 wa = s_w2[2 * p2];
        uint4 wb = s_w2[2 * p2 + 1];
        int k0 = __popc(sw[0] ^ wa.x) + __popc(sw[1] ^ wa.y) +
                 __popc(sw[2] ^ wa.z) + __popc(sw[3] ^ wa.w);
        int k1 = __popc(sw[0] ^ wb.x) + __popc(sw[1] ^ wb.y) +
                 __popc(sw[2] ^ wb.z) + __popc(sw[3] ^ wb.w);
        *(uchar2*)(outp + ((size_t)p2 << 17)) =
            make_uchar2((unsigned char)k0, (unsigned char)k1);
    }
}

// ---------------- stats for BN2 from interleaved k bytes (masked dp4a) --------------
// Block order reversed: reads freshest (L2-resident) k2p first.
__global__ void k_stats2() {
    int b = (int)gridDim.x - 1 - (int)blockIdx.x;   // b = n*32 + pair, reversed
    int pair = b & 31;
    int t = threadIdx.x;
    const uint4* ptr = (const uint4*)(g_k2p + ((size_t)b << 17));
    unsigned s0 = 0u, s1 = 0u, q0 = 0u, q1 = 0u;
    #pragma unroll 4
    for (int i = 0; i < 32; i++) {
        uint4 v = ptr[t + i * 256];
        #pragma unroll
        for (int wsel = 0; wsel < 4; wsel++) {
            unsigned w = (wsel == 0) ? v.x : (wsel == 1) ? v.y :
                         (wsel == 2) ? v.z : v.w;
            unsigned we = w & 0x00FF00FFu;          // even channel (2p)
            unsigned wo = (w >> 8) & 0x00FF00FFu;   // odd channel (2p+1)
            s0 = __dp4a(we, 0x01010101u, s0);  q0 = __dp4a(we, we, q0);
            s1 = __dp4a(wo, 0x01010101u, s1);  q1 = __dp4a(wo, wo, q1);
        }
    }
    s0 = __reduce_add_sync(0xFFFFFFFFu, s0);
    q0 = __reduce_add_sync(0xFFFFFFFFu, q0);
    s1 = __reduce_add_sync(0xFFFFFFFFu, s1);
    q1 = __reduce_add_sync(0xFFFFFFFFu, q1);
    __shared__ unsigned sh_s0, sh_q0, sh_s1, sh_q1;
    if (t == 0) { sh_s0 = 0u; sh_q0 = 0u; sh_s1 = 0u; sh_q1 = 0u; }
    __syncthreads();
    if ((t & 31) == 0) {
        atomicAdd(&sh_s0, s0); atomicAdd(&sh_q0, q0);
        atomicAdd(&sh_s1, s1); atomicAdd(&sh_q1, q1);
    }
    __syncthreads();
    if (t == 0) {
        atomicAdd(&g_sk[2 * pair],     (unsigned long long)sh_s0);
        atomicAdd(&g_qk[2 * pair],     (unsigned long long)sh_q0);
        atomicAdd(&g_sk[2 * pair + 1], (unsigned long long)sh_s1);
        atomicAdd(&g_qk[2 * pair + 1], (unsigned long long)sh_q1);
    }
}

// ---------------- finalize BN2 -> affine h2(k) = lrelu(P*k + Q) ----------------
__global__ void k_fin2(const float* __restrict__ g2, const float* __restrict__ b2) {
    int c = threadIdx.x;
    if (c >= C2) return;
    double N = (double)NPIX;
    double mk = (double)(long long)g_sk[c] / N;
    double qk = (double)g_qk[c] / N;
    double vark = qk - mk * mk;
    float meanv = (float)(128.0 - 2.0 * mk);
    float varv  = (float)(4.0 * vark);
    float inv   = g2[c] * rsqrtf(varv + 1e-5f);
    g_P[c] = -2.f * inv;
    g_Q[c] = (128.f - meanv) * inv + b2[c];
}

// ---------------- layer 3: fp32 5x5 conv, 64 ch -> 1 ch, f32x2-packed ----------------
// 32x64 tile (8 output rows x 2 cols per thread): 512 blocks = one wave at 4/SM.
// Fill loop now free to unroll (MLP >= 4 hides L2/DRAM latency between syncs).
__global__ void __launch_bounds__(128, 4) k_conv3(const float* __restrict__ w3,
                                                  float* __restrict__ out) {
    __shared__ float ht2[2][68][72];    // 39,168 B  [pairLocal][row][2*col+sub]
    __shared__ float w3p[32][25][2];    //  6,400 B  weight pairs
    __shared__ float Ps[C2], Qs[C2];    //    512 B
    int t  = threadIdx.x;               // 0..127
    int tx = t & 15;                    // 0..15 : cols 2*tx
    int ty = t >> 4;                    // 0..7  : rows 8*ty
    for (int i = t; i < 1600; i += 128) {
        int pp = i / 50;
        int rm = i % 50;
        int tap = rm >> 1;
        int sub = rm & 1;
        w3p[pp][tap][sub] = w3[(2 * pp + sub) * 25 + tap];
    }
    if (t < C2) { Ps[t] = g_P[t]; Qs[t] = g_Q[t]; }

    int n = blockIdx.z;
    int X0 = blockIdx.x * 32;
    int Y0 = blockIdx.y * 64;
    const unsigned char* kpbase = g_k2p + ((size_t)n << 22);

    unsigned long long acc[8][2];
    #pragma unroll
    for (int ry = 0; ry < 8; ry++) { acc[ry][0] = 0ull; acc[ry][1] = 0ull; }

    #pragma unroll 1
    for (int s = 0; s < 16; s++) {
        __syncthreads();                // previous stage fully consumed (also covers w3p)
        // fill 68x36 halo tile for pairs 2s, 2s+1: one LDG.32 = 2 px x 2 ch
        #pragma unroll 4
        for (int i = t; i < 68 * 18; i += 128) {    // 68 rows x 18 x-pairs
            int yy = i / 18;
            int xp = i - yy * 18;
            int xx = xp << 1;
            int gy = Y0 - 2 + yy;
            int gx = X0 - 2 + xx;                   // always even
            bool ok = ((unsigned)gy < 256u) && ((unsigned)gx < 256u);
            size_t off2 = 2 * (size_t)(gy * 256 + gx);
            #pragma unroll
            for (int pl = 0; pl < 2; pl++) {
                int pidx = 2 * s + pl;
                float4 v = make_float4(0.f, 0.f, 0.f, 0.f);
                if (ok) {
                    unsigned w = *(const unsigned*)(kpbase +
                                    (((size_t)pidx) << 17) + off2);
                    int ca = 2 * pidx;
                    float h0 = fmaf(Ps[ca],     (float)(w & 255u),         Qs[ca]);
                    float h1 = fmaf(Ps[ca + 1], (float)((w >> 8) & 255u),  Qs[ca + 1]);
                    float h2 = fmaf(Ps[ca],     (float)((w >> 16) & 255u), Qs[ca]);
                    float h3 = fmaf(Ps[ca + 1], (float)(w >> 24),          Qs[ca + 1]);
                    v = make_float4(fmaxf(h0, 0.5f * h0), fmaxf(h1, 0.5f * h1),
                                    fmaxf(h2, 0.5f * h2), fmaxf(h3, 0.5f * h3));
                }
                *(float4*)&ht2[pl][yy][2 * xx] = v;
            }
        }
        __syncthreads();

        #pragma unroll
        for (int pl = 0; pl < 2; pl++) {
            unsigned long long wp[25];
            const unsigned long long* wbp =
                (const unsigned long long*)&w3p[2 * s + pl][0][0];
            #pragma unroll
            for (int tap = 0; tap < 25; tap++) wp[tap] = wbp[tap];

            #pragma unroll
            for (int rr = 0; rr < 12; rr++) {
                const float* rowp = &ht2[pl][ty * 8 + rr][4 * tx];
                ulonglong2 q0 = *(const ulonglong2*)(rowp);
                ulonglong2 q1 = *(const ulonglong2*)(rowp + 4);
                ulonglong2 q2 = *(const ulonglong2*)(rowp + 8);
                unsigned long long P0 = q0.x, P1 = q0.y, P2 = q1.x,
                                   P3 = q1.y, P4 = q2.x, P5 = q2.y;
                #pragma unroll
                for (int ky = 0; ky < 5; ky++) {
                    int ry = rr - ky;
                    if (ry >= 0 && ry < 8) {
                        unsigned long long w0 = wp[ky * 5 + 0];
                        unsigned long long w1 = wp[ky * 5 + 1];
                        unsigned long long w2 = wp[ky * 5 + 2];
                        unsigned long long w3v = wp[ky * 5 + 3];
                        unsigned long long w4 = wp[ky * 5 + 4];
                        acc[ry][0] = fma2(P0, w0, acc[ry][0]);
                        acc[ry][1] = fma2(P1, w0, acc[ry][1]);
                        acc[ry][0] = fma2(P1, w1, acc[ry][0]);
                        acc[ry][1] = fma2(P2, w1, acc[ry][1]);
                        acc[ry][0] = fma2(P2, w2, acc[ry][0]);
                        acc[ry][1] = fma2(P3, w2, acc[ry][1]);
                        acc[ry][0] = fma2(P3, w3v, acc[ry][0]);
                        acc[ry][1] = fma2(P4, w3v, acc[ry][1]);
                        acc[ry][0] = fma2(P4, w4, acc[ry][0]);
                        acc[ry][1] = fma2(P5, w4, acc[ry][1]);
                    }
                }
            }
        }
    }

    #pragma unroll
    for (int ry = 0; ry < 8; ry++) {
        int yo = Y0 + ty * 8 + ry;
        float r0 = __uint_as_float((unsigned)acc[ry][0]) +
                   __uint_as_float((unsigned)(acc[ry][0] >> 32));
        float r1 = __uint_as_float((unsigned)acc[ry][1]) +
                   __uint_as_float((unsigned)(acc[ry][1] >> 32));
        *(float2*)&out[(n << 16) + yo * 256 + X0 + 2 * tx] = make_float2(r0, r1);
    }
}

// ---------------- launch ----------------
extern "C" void kernel_launch(void* const* d_in, const int* in_sizes, int n_in,
                              void* d_out, int out_size) {
    const float* x  = (const float*)d_in[0];
    const float* w1 = (const float*)d_in[1];
    const float* g1 = (const float*)d_in[2];
    const float* b1 = (const float*)d_in[3];
    const float* w2 = (const float*)d_in[4];
    const float* g2 = (const float*)d_in[5];
    const float* b2 = (const float*)d_in[6];
    const float* w3 = (const float*)d_in[7];
    float* out = (float*)d_out;

    k_packx<<<NPIX / 256, 256>>>(x, w1, w2);
    k_conv1_stats<<<NPIX / 2048, 256>>>();
    k_fin1<<<1, 128>>>(g1, b1);
    k_sign_conv2<<<NPIX / 256, 256>>>();
    k_stats2<<<NB * 32, 256>>>();
    k_fin2<<<1, 64>>>(g2, b2);
    k_conv3<<<dim3(8, 4, NB), 128>>>(w3, out);
    (void)in_sizes; (void)n_in; (void)out_size;
}

// round 16
// speedup vs baseline: 1.0438x; 1.0438x over previous
#include <cuda_runtime.h>
#include <cuda_pipeline.h>
#include <cstdint>
#include <cstddef>

#define NB 16
#define HH 256
#define WW 256
#define NPIX (NB * HH * WW)        // 1,048,576 pixels (per-channel BN count)
#define C1 128
#define C2 64

// ---------------- static device scratch (no allocations allowed) ----------------
__device__ uint32_t           g_xbits[NB * HH * (WW / 32)];   // packed sign(x), 128KB
__device__ unsigned long long g_wb1[C1];                      // 49-bit weight signs, layer1
__device__ uint4              g_wb2[C2];                      // 128-bit weight signs, layer2
__device__ unsigned long long g_s1[C1];                       // sum v1 (2's complement)
__device__ unsigned long long g_q1[C1];                       // sum v1^2
__device__ int                g_lo[C1];                       // v-interval lo (border path)
__device__ int                g_wd[C1];                       // v-interval width
__device__ int                g_ilo[C1];                      // d-interval lo (interior path)
__device__ int                g_iwd[C1];                      // d-interval width
__device__ unsigned long long g_sk[C2];                       // sum k
__device__ unsigned long long g_qk[C2];                       // sum k^2
__device__ float              g_P[C2], g_Q[C2];               // h2 = lrelu(P*k + Q)
__device__ uint32_t           g_d1[(size_t)32 * NPIX];        // 128MB: d packed 4ch/word, [cg][px]
// layer2 popcounts, channel-PAIR interleaved: [n][pair][px] as uchar2 (64MB)
__device__ unsigned char      g_k2p[(size_t)NB * 32 * HH * WW * 2];

// ---------------- packed f32x2 FMA (SASS FFMA2: 2 exact fp32 FMAs / issue slot) -----
__device__ __forceinline__ unsigned long long fma2(unsigned long long a,
                                                   unsigned long long b,
                                                   unsigned long long c) {
    unsigned long long d;
    asm("fma.rn.f32x2 %0, %1, %2, %3;" : "=l"(d) : "l"(a), "l"(b), "l"(c));
    return d;
}

// ---------------- pack sign(x) into bitmap; block 0 also packs weights + zeroes stats
__global__ void k_packx(const float* __restrict__ x,
                        const float* __restrict__ w1,
                        const float* __restrict__ w2) {
    int t = threadIdx.x;
    if (blockIdx.x == 0) {
        if (t < C1) {
            unsigned long long b = 0ull;
            #pragma unroll
            for (int j = 0; j < 49; j++)
                if (w1[t * 49 + j] >= 0.f) b |= (1ull << j);
            g_wb1[t] = b;
            g_s1[t] = 0ull;
            g_q1[t] = 0ull;
        }
        if (t < C2) {
            uint32_t w[4];
            #pragma unroll
            for (int q = 0; q < 4; q++) {
                uint32_t b = 0u;
                #pragma unroll
                for (int j = 0; j < 32; j++)
                    if (w2[t * 128 + q * 32 + j] >= 0.f) b |= (1u << j);
                w[q] = b;
            }
            g_wb2[t] = make_uint4(w[0], w[1], w[2], w[3]);
            g_sk[t] = 0ull;
            g_qk[t] = 0ull;
        }
    }
    int idx = blockIdx.x * 256 + t;
    unsigned b = __ballot_sync(0xFFFFFFFFu, x[idx] >= 0.f);
    if ((t & 31) == 0) g_xbits[idx >> 5] = b;
}

// ---------------- 7x7 window of sign bits + validity mask (border-safe) -------------
__device__ __forceinline__ void build_window(int n, int y, int x,
                                             unsigned long long& win,
                                             unsigned long long& msk) {
    const uint32_t* rowbase = g_xbits + (n << 11);
    uint32_t colmask = 0x7Fu;
    if (x < 3)   colmask &= (0x7Fu << (3 - x));
    if (x > 252) colmask &= (0x7Fu >> (x - 252));
    colmask &= 0x7Fu;
    int base = x - 3;
    int wi = (base >= 0) ? (base >> 5) : -1;
    int sh = base & 31;
    win = 0ull; msk = 0ull;
    #pragma unroll
    for (int r = 0; r < 7; r++) {
        int yy = y + r - 3;
        if (yy >= 0 && yy < HH) {
            const uint32_t* rw = rowbase + (yy << 3);
            uint32_t w0 = (wi >= 0) ? rw[wi] : 0u;
            uint32_t w1 = (wi < 7) ? rw[wi + 1] : 0u;
            uint32_t bits = __funnelshift_r(w0, w1, sh) & colmask;
            win |= (unsigned long long)bits << (7 * r);
            msk |= (unsigned long long)colmask << (7 * r);
        }
    }
}

// ---------------- unguarded interior window from shared row bits --------------------
__device__ __forceinline__ unsigned long long win_from_rows(const uint32_t* rb) {
    unsigned long long w = 0ull;
    #pragma unroll
    for (int r = 0; r < 7; r++)
        w |= (unsigned long long)rb[r] << (7 * r);
    return w;
}

// ---------------- pass 1: layer1 conv -> per-channel integer stats + packed d store --
__global__ void k_conv1_stats() {
    __shared__ unsigned long long s_wb[C1];
    __shared__ int s_sum[C1];
    __shared__ int s_sq[C1];
    int t = threadIdx.x;
    if (t < C1) { s_wb[t] = g_wb1[t]; s_sum[t] = 0; s_sq[t] = 0; }
    __syncthreads();

    int base = blockIdx.x * 2048 + t;
    int n  = base >> 16;
    int r0 = (blockIdx.x * 8) & 255;     // first of 8 rows this block covers
    int x  = t;                          // column (block spans full rows)
    int lane = t & 31;
    int xw = t & 224;                    // warp x-start (multiple of 32)
    bool wint = (xw != 0) && (xw != 224) && (r0 >= 8) && (r0 <= 240);

    if (wint) {
        // ---- interior fast path: unmasked windows ----
        const uint32_t* rowbase = g_xbits + (n << 11);
        int bm3 = x - 3;
        int wi = bm3 >> 5;
        int sh = bm3 & 31;
        uint32_t rb[14];
        #pragma unroll
        for (int j = 0; j < 14; j++) {
            const uint32_t* rw = rowbase + ((r0 - 3 + j) << 3);
            rb[j] = __funnelshift_r(rw[wi], rw[wi + 1], sh) & 0x7Fu;
        }
        unsigned long long win[8];
        #pragma unroll
        for (int k = 0; k < 8; k++) win[k] = win_from_rows(rb + k);

        #pragma unroll 2
        for (int cg = 0; cg < 32; cg++) {
            unsigned long long wb0 = s_wb[4 * cg + 0];
            unsigned long long wb1 = s_wb[4 * cg + 1];
            unsigned long long wb2 = s_wb[4 * cg + 2];
            unsigned long long wb3 = s_wb[4 * cg + 3];
            int sd0 = 0, sd1 = 0, sd2 = 0, sd3 = 0;
            int q0 = 0, q1 = 0, q2 = 0, q3 = 0;
            #pragma unroll
            for (int k = 0; k < 8; k++) {
                int d0 = __popcll(win[k] ^ wb0);
                int d1 = __popcll(win[k] ^ wb1);
                int d2 = __popcll(win[k] ^ wb2);
                int d3 = __popcll(win[k] ^ wb3);
                sd0 += d0; q0 += d0 * d0;
                sd1 += d1; q1 += d1 * d1;
                sd2 += d2; q2 += d2 * d2;
                sd3 += d3; q3 += d3 * d3;
                g_d1[((size_t)cg << 20) + base + k * 256] =
                    (unsigned)d0 | ((unsigned)d1 << 8) |
                    ((unsigned)d2 << 16) | ((unsigned)d3 << 24);
            }
            #pragma unroll
            for (int j = 0; j < 4; j++) {
                int sd = (j == 0) ? sd0 : (j == 1) ? sd1 : (j == 2) ? sd2 : sd3;
                int qq = (j == 0) ? q0  : (j == 1) ? q1  : (j == 2) ? q2  : q3;
                int Sd  = __reduce_add_sync(0xFFFFFFFFu, sd);
                int Sdd = __reduce_add_sync(0xFFFFFFFFu, qq);
                if (lane == 0) {
                    // 256 px/warp: sum v = 256*49 - 2*Sd ; sum v^2 = 256*2401 - 196*Sd + 4*Sdd
                    atomicAdd(&s_sum[4 * cg + j], 12544 - 2 * Sd);
                    atomicAdd(&s_sq[4 * cg + j], 614656 - 196 * Sd + 4 * Sdd);
                }
            }
        }
    } else {
        // ---- border path (exact masks) ----
        unsigned long long win[8], msk[8];
        int inb[8];
        #pragma unroll
        for (int k = 0; k < 8; k++) {
            int p = base + k * 256;
            int rem = p & 65535;
            build_window(n, rem >> 8, rem & 255, win[k], msk[k]);
            inb[k] = __popcll(msk[k]);
        }
        #pragma unroll 2
        for (int cg = 0; cg < 32; cg++) {
            unsigned long long wb0 = s_wb[4 * cg + 0];
            unsigned long long wb1 = s_wb[4 * cg + 1];
            unsigned long long wb2 = s_wb[4 * cg + 2];
            unsigned long long wb3 = s_wb[4 * cg + 3];
            int s0 = 0, s1 = 0, s2 = 0, s3 = 0;
            int q0 = 0, q1 = 0, q2 = 0, q3 = 0;
            #pragma unroll
            for (int k = 0; k < 8; k++) {
                int d0 = __popcll((win[k] ^ wb0) & msk[k]);
                int d1 = __popcll((win[k] ^ wb1) & msk[k]);
                int d2 = __popcll((win[k] ^ wb2) & msk[k]);
                int d3 = __popcll((win[k] ^ wb3) & msk[k]);
                g_d1[((size_t)cg << 20) + base + k * 256] =
                    (unsigned)d0 | ((unsigned)d1 << 8) |
                    ((unsigned)d2 << 16) | ((unsigned)d3 << 24);
                int v0 = inb[k] - 2 * d0;
                int v1 = inb[k] - 2 * d1;
                int v2 = inb[k] - 2 * d2;
                int v3 = inb[k] - 2 * d3;
                s0 += v0; q0 += v0 * v0;
                s1 += v1; q1 += v1 * v1;
                s2 += v2; q2 += v2 * v2;
                s3 += v3; q3 += v3 * v3;
            }
            #pragma unroll
            for (int j = 0; j < 4; j++) {
                int ss = (j == 0) ? s0 : (j == 1) ? s1 : (j == 2) ? s2 : s3;
                int qq = (j == 0) ? q0 : (j == 1) ? q1 : (j == 2) ? q2 : q3;
                int S  = __reduce_add_sync(0xFFFFFFFFu, ss);
                int Q  = __reduce_add_sync(0xFFFFFFFFu, qq);
                if (lane == 0) {
                    atomicAdd(&s_sum[4 * cg + j], S);
                    atomicAdd(&s_sq[4 * cg + j], Q);
                }
            }
        }
    }
    __syncthreads();
    if (t < C1) {
        atomicAdd(&g_s1[t], (unsigned long long)(long long)s_sum[t]);
        atomicAdd(&g_q1[t], (unsigned long long)(long long)s_sq[t]);
    }
}

// ---------------- finalize BN1 -> sign-threshold intervals (v and d domains) --------
__global__ void k_fin1(const float* __restrict__ g1, const float* __restrict__ b1) {
    int c = threadIdx.x;
    if (c >= C1) return;
    double N = (double)NPIX;
    double S1 = (double)(long long)g_s1[c];
    double S2 = (double)g_q1[c];
    double mean = S1 / N;
    double var  = S2 / N - mean * mean;
    float meanf = (float)mean;
    float invf  = g1[c] * rsqrtf((float)var + 1e-5f);
    float beta  = b1[c];
    int lo = 100, hi = -100;
    bool any = false;
    for (int v = -49; v <= 49; v++) {
        float h = ((float)v - meanf) * invf + beta;
        if (h >= 0.f) { if (!any) { lo = v; any = true; } hi = v; }
    }
    int ilo = 100, iwd = 0;                 // d-interval for interior (v = 49-2d)
    if (!any) { g_lo[c] = 100; g_wd[c] = 0; }
    else {
        g_lo[c] = lo;  g_wd[c] = hi - lo;
        int dlo = (49 - hi + 1) >> 1;       // ceil((49-hi)/2)
        int dhi = (49 - lo) >> 1;           // floor((49-lo)/2)
        if (dlo < 0) dlo = 0;
        if (dhi > 49) dhi = 49;
        if (dhi >= dlo) { ilo = dlo; iwd = dhi - dlo; }
    }
    g_ilo[c] = ilo; g_iwd[c] = iwd;
}

// ---------------- pass 2: stored d -> SWAR threshold -> layer2 1x1 binary conv ------
// (exact R11/R14 version: regs 38, occ ~60% — measured local optimum)
__global__ void k_sign_conv2() {
    __shared__ unsigned long long s_wb[C1];
    __shared__ int2 s_vi[C1];          // (lo, wd)  border, v-domain
    __shared__ unsigned s_LO[32];      // packed lo bytes (4 ch/word)
    __shared__ unsigned s_HIO[32];     // packed (hi|0x80) bytes
    __shared__ uint4 s_w2[C2];
    int t = threadIdx.x;
    if (t < C1) {
        s_wb[t] = g_wb1[t];
        s_vi[t] = make_int2(g_lo[t], g_wd[t]);
    }
    if (t < 32) {
        unsigned lo = 0, hio = 0;
        #pragma unroll
        for (int j = 0; j < 4; j++) {
            int c = 4 * t + j;
            lo  |= (unsigned)g_ilo[c] << (8 * j);
            hio |= (unsigned)((g_ilo[c] + g_iwd[c]) | 0x80) << (8 * j);
        }
        s_LO[t] = lo; s_HIO[t] = hio;
    }
    if (t < C2) s_w2[t] = g_wb2[t];
    __syncthreads();

    int p = blockIdx.x * 256 + t;
    int n = p >> 16;
    int rem = p & 65535;
    int y = rem >> 8;                  // block-uniform (one row per block)
    int xw = t & 224;
    bool wint = (xw != 0) && (xw != 224) && (y >= 3) && (y <= 252);

    uint32_t sw[4];
    if (wint) {
        unsigned m0 = 0, m1 = 0, m2 = 0, m3 = 0;
        #pragma unroll
        for (int cg = 0; cg < 32; cg++) {
            unsigned D = g_d1[((size_t)cg << 20) + p];
            unsigned ge = (D | 0x80808080u) - s_LO[cg];
            unsigned le = s_HIO[cg] - D;
            unsigned both = ge & le & 0x80808080u;
            unsigned nib = (((both >> 7) * 0x01020408u) >> 24) & 0xFu;
            unsigned sh = 4 * (cg & 7);
            if ((cg >> 3) == 0) m0 |= nib << sh;
            else if ((cg >> 3) == 1) m1 |= nib << sh;
            else if ((cg >> 3) == 2) m2 |= nib << sh;
            else m3 |= nib << sh;
        }
        sw[0] = m0; sw[1] = m1; sw[2] = m2; sw[3] = m3;
    } else {
        unsigned long long win, msk;
        build_window(n, y, t, win, msk);
        int inb = __popcll(msk);
        #pragma unroll
        for (int w = 0; w < 4; w++) {
            uint32_t bits = 0u;
            #pragma unroll
            for (int j = 0; j < 32; j++) {
                int c = w * 32 + j;
                int dis = __popcll((win ^ s_wb[c]) & msk);
                int v = inb - 2 * dis;
                int2 vi = s_vi[c];
                if ((unsigned)(v - vi.x) <= (unsigned)vi.y) bits |= (1u << j);
            }
            sw[w] = bits;
        }
    }

    unsigned char* outp = g_k2p + ((size_t)n << 22) + 2 * (size_t)rem;
    #pragma unroll 8
    for (int p2 = 0; p2 < 32; p2++) {
        uint4 wa = s_w2[2 * p2];
        uint4 wb = s_w2[2 * p2 + 1];
        int k0 = __popc(sw[0] ^ wa.x) + __popc(sw[1] ^ wa.y) +
                 __popc(sw[2] ^ wa.z) + __popc(sw[3] ^ wa.w);
        int k1 = __popc(sw[0] ^ wb.x) + __popc(sw[1] ^ wb.y) +
                 __popc(sw[2] ^ wb.z) + __popc(sw[3] ^ wb.w);
        *(uchar2*)(outp + ((size_t)p2 << 17)) =
            make_uchar2((unsigned char)k0, (unsigned char)k1);
    }
}

// ---------------- stats for BN2 from interleaved k bytes (masked dp4a) --------------
__global__ void k_stats2() {
    int b = blockIdx.x;           // b = n*32 + pair
    int pair = b & 31;
    int t = threadIdx.x;
    const uint4* ptr = (const uint4*)(g_k2p + ((size_t)b << 17));
    unsigned s0 = 0u, s1 = 0u, q0 = 0u, q1 = 0u;
    #pragma unroll 4
    for (int i = 0; i < 32; i++) {
        uint4 v = ptr[t + i * 256];
        #pragma unroll
        for (int wsel = 0; wsel < 4; wsel++) {
            unsigned w = (wsel == 0) ? v.x : (wsel == 1) ? v.y :
                         (wsel == 2) ? v.z : v.w;
            unsigned we = w & 0x00FF00FFu;          // even channel (2p)
            unsigned wo = (w >> 8) & 0x00FF00FFu;   // odd channel (2p+1)
            s0 = __dp4a(we, 0x01010101u, s0);  q0 = __dp4a(we, we, q0);
            s1 = __dp4a(wo, 0x01010101u, s1);  q1 = __dp4a(wo, wo, q1);
        }
    }
    s0 = __reduce_add_sync(0xFFFFFFFFu, s0);
    q0 = __reduce_add_sync(0xFFFFFFFFu, q0);
    s1 = __reduce_add_sync(0xFFFFFFFFu, s1);
    q1 = __reduce_add_sync(0xFFFFFFFFu, q1);
    __shared__ unsigned sh_s0, sh_q0, sh_s1, sh_q1;
    if (t == 0) { sh_s0 = 0u; sh_q0 = 0u; sh_s1 = 0u; sh_q1 = 0u; }
    __syncthreads();
    if ((t & 31) == 0) {
        atomicAdd(&sh_s0, s0); atomicAdd(&sh_q0, q0);
        atomicAdd(&sh_s1, s1); atomicAdd(&sh_q1, q1);
    }
    __syncthreads();
    if (t == 0) {
        atomicAdd(&g_sk[2 * pair],     (unsigned long long)sh_s0);
        atomicAdd(&g_qk[2 * pair],     (unsigned long long)sh_q0);
        atomicAdd(&g_sk[2 * pair + 1], (unsigned long long)sh_s1);
        atomicAdd(&g_qk[2 * pair + 1], (unsigned long long)sh_q1);
    }
}

// ---------------- finalize BN2 -> affine h2(k) = lrelu(P*k + Q) ----------------
__global__ void k_fin2(const float* __restrict__ g2, const float* __restrict__ b2) {
    int c = threadIdx.x;
    if (c >= C2) return;
    double N = (double)NPIX;
    double mk = (double)(long long)g_sk[c] / N;
    double qk = (double)g_qk[c] / N;
    double vark = qk - mk * mk;
    float meanv = (float)(128.0 - 2.0 * mk);
    float varv  = (float)(4.0 * vark);
    float inv   = g2[c] * rsqrtf(varv + 1e-5f);
    g_P[c] = -2.f * inv;
    g_Q[c] = (128.f - meanv) * inv + b2[c];
}

// ---------------- layer 3: fp32 5x5 conv, 64 ch -> 1 ch, f32x2 + cp.async pipeline ---
// 32x64 tile, 32 single-pair stages. Stage s+1's raw k-words are prefetched
// global->shared with cp.async (no registers, latency hidden under compute(s));
// a short convert pass (LDS raw -> lrelu float -> STS) replaces the synchronous
// LDG fill. smem: ht2 19.6KB + raw ping-pong 9.8KB + weights 6.9KB = 36.3KB.
__global__ void __launch_bounds__(128, 4) k_conv3(const float* __restrict__ w3,
                                                  float* __restrict__ out) {
    __shared__ float    ht2[68][72];    // 19,584 B  one channel-pair, [row][2*col+sub]
    __shared__ uint32_t rawb[2][1224];  //  9,792 B  raw k-words ping-pong (68x18 items)
    __shared__ float    w3p[32][25][2]; //  6,400 B  weight pairs
    __shared__ float    Ps[C2], Qs[C2]; //    512 B
    int t  = threadIdx.x;               // 0..127
    int tx = t & 15;                    // 0..15 : cols 2*tx
    int ty = t >> 4;                    // 0..7  : rows 8*ty
    for (int i = t; i < 1600; i += 128) {
        int pp = i / 50;
        int rm = i % 50;
        int tap = rm >> 1;
        int sub = rm & 1;
        w3p[pp][tap][sub] = w3[(2 * pp + sub) * 25 + tap];
    }
    if (t < C2) { Ps[t] = g_P[t]; Qs[t] = g_Q[t]; }

    int n = blockIdx.z;
    int X0 = blockIdx.x * 32;
    int Y0 = blockIdx.y * 64;
    const unsigned char* kpbase = g_k2p + ((size_t)n << 22);

    unsigned long long acc[8][2];
    #pragma unroll
    for (int ry = 0; ry < 8; ry++) { acc[ry][0] = 0ull; acc[ry][1] = 0ull; }

    // async prefetch of pair s's raw words into rawb[b]
    auto prefetch = [&](int s, int b) {
        const unsigned char* pb = kpbase + ((size_t)s << 17);
        #pragma unroll 1
        for (int i = t; i < 1224; i += 128) {       // 68 rows x 18 x-pairs
            int yy = i / 18;
            int xp = i - yy * 18;
            int gy = Y0 - 2 + yy;
            int gx = X0 - 2 + (xp << 1);            // always even
            if (((unsigned)gy < 256u) && ((unsigned)gx < 256u))
                __pipeline_memcpy_async(&rawb[b][i],
                                        pb + 2 * (size_t)(gy * 256 + gx), 4);
        }
        __pipeline_commit();
    };

    prefetch(0, 0);

    #pragma unroll 1
    for (int s = 0; s < 32; s++) {
        if (s + 1 < 32) prefetch(s + 1, (s + 1) & 1);
        __pipeline_wait_prior((s + 1 < 32) ? 1 : 0);   // stage s's group complete
        __syncthreads();    // all threads' copies visible; compute(s-1) done with ht2

        // convert raw words -> lrelu floats in ht2
        int ca = 2 * s;
        float Pa = Ps[ca], Qa = Qs[ca], Pb = Ps[ca + 1], Qb = Qs[ca + 1];
        #pragma unroll 1
        for (int i = t; i < 1224; i += 128) {
            int yy = i / 18;
            int xp = i - yy * 18;
            int gy = Y0 - 2 + yy;
            int gx = X0 - 2 + (xp << 1);
            float4 v = make_float4(0.f, 0.f, 0.f, 0.f);
            if (((unsigned)gy < 256u) && ((unsigned)gx < 256u)) {
                unsigned w = rawb[s & 1][i];
                float h0 = fmaf(Pa, (float)(w & 255u),         Qa);
                float h1 = fmaf(Pb, (float)((w >> 8) & 255u),  Qb);
                float h2 = fmaf(Pa, (float)((w >> 16) & 255u), Qa);
                float h3 = fmaf(Pb, (float)(w >> 24),          Qb);
                v = make_float4(fmaxf(h0, 0.5f * h0), fmaxf(h1, 0.5f * h1),
                                fmaxf(h2, 0.5f * h2), fmaxf(h3, 0.5f * h3));
            }
            *(float4*)&ht2[yy][4 * xp] = v;
        }
        __syncthreads();

        // compute this pair (overlaps with the in-flight cp.async of stage s+1)
        unsigned long long wp[25];
        const unsigned long long* wbp = (const unsigned long long*)&w3p[s][0][0];
        #pragma unroll
        for (int tap = 0; tap < 25; tap++) wp[tap] = wbp[tap];

        #pragma unroll
        for (int rr = 0; rr < 12; rr++) {
            const float* rowp = &ht2[ty * 8 + rr][4 * tx];
            ulonglong2 q0 = *(const ulonglong2*)(rowp);
            ulonglong2 q1 = *(const ulonglong2*)(rowp + 4);
            ulonglong2 q2 = *(const ulonglong2*)(rowp + 8);
            unsigned long long P0 = q0.x, P1 = q0.y, P2 = q1.x,
                               P3 = q1.y, P4 = q2.x, P5 = q2.y;
            #pragma unroll
            for (int ky = 0; ky < 5; ky++) {
                int ry = rr - ky;
                if (ry >= 0 && ry < 8) {
                    unsigned long long w0 = wp[ky * 5 + 0];
                    unsigned long long w1 = wp[ky * 5 + 1];
                    unsigned long long w2 = wp[ky * 5 + 2];
                    unsigned long long w3v = wp[ky * 5 + 3];
                    unsigned long long w4 = wp[ky * 5 + 4];
                    acc[ry][0] = fma2(P0, w0, acc[ry][0]);
                    acc[ry][1] = fma2(P1, w0, acc[ry][1]);
                    acc[ry][0] = fma2(P1, w1, acc[ry][0]);
                    acc[ry][1] = fma2(P2, w1, acc[ry][1]);
                    acc[ry][0] = fma2(P2, w2, acc[ry][0]);
                    acc[ry][1] = fma2(P3, w2, acc[ry][1]);
                    acc[ry][0] = fma2(P3, w3v, acc[ry][0]);
                    acc[ry][1] = fma2(P4, w3v, acc[ry][1]);
                    acc[ry][0] = fma2(P4, w4, acc[ry][0]);
                    acc[ry][1] = fma2(P5, w4, acc[ry][1]);
                }
            }
        }
    }

    #pragma unroll
    for (int ry = 0; ry < 8; ry++) {
        int yo = Y0 + ty * 8 + ry;
        float r0 = __uint_as_float((unsigned)acc[ry][0]) +
                   __uint_as_float((unsigned)(acc[ry][0] >> 32));
        float r1 = __uint_as_float((unsigned)acc[ry][1]) +
                   __uint_as_float((unsigned)(acc[ry][1] >> 32));
        *(float2*)&out[(n << 16) + yo * 256 + X0 + 2 * tx] = make_float2(r0, r1);
    }
}

// ---------------- launch ----------------
extern "C" void kernel_launch(void* const* d_in, const int* in_sizes, int n_in,
                              void* d_out, int out_size) {
    const float* x  = (const float*)d_in[0];
    const float* w1 = (const float*)d_in[1];
    const float* g1 = (const float*)d_in[2];
    const float* b1 = (const float*)d_in[3];
    const float* w2 = (const float*)d_in[4];
    const float* g2 = (const float*)d_in[5];
    const float* b2 = (const float*)d_in[6];
    const float* w3 = (const float*)d_in[7];
    float* out = (float*)d_out;

    k_packx<<<NPIX / 256, 256>>>(x, w1, w2);
    k_conv1_stats<<<NPIX / 2048, 256>>>();
    k_fin1<<<1, 128>>>(g1, b1);
    k_sign_conv2<<<NPIX / 256, 256>>>();
    k_stats2<<<NB * 32, 256>>>();
    k_fin2<<<1, 64>>>(g2, b2);
    k_conv3<<<dim3(8, 4, NB), 128>>>(w3, out);
    (void)in_sizes; (void)n_in; (void)out_size;
}